// round 3
// baseline (speedup 1.0000x reference)
#include <cuda_runtime.h>
#include <cuda_bf16.h>

#define N_NODES 100000
#define NPAD    100096          // 782 * 128, pads GEMM M dimension
#define NE      500000
#define C       256
#define K4      1024            // 4 * 256 concatenated aggregation

// ---------------- scratch (device globals, zero-initialized at load) -------
__device__ __align__(16) float g_agg[(size_t)NPAD * K4];   // [NPAD, 1024]
__device__ int   g_deg[4][N_NODES];
__device__ float g_dis[4][N_NODES];
__device__ __align__(16) float g_Wcat[K4 * C];             // [1024, 256]
__device__ float g_bias[C];

// ---------------- helpers --------------------------------------------------
__device__ __forceinline__ void red_add_v4(float* addr, float4 v) {
    asm volatile("red.global.add.v4.f32 [%0], {%1,%2,%3,%4};"
                 :: "l"(addr), "f"(v.x), "f"(v.y), "f"(v.z), "f"(v.w)
                 : "memory");
}

// ---------------- kernels --------------------------------------------------
__global__ void k_init_deg() {
    int i = blockIdx.x * blockDim.x + threadIdx.x;
    if (i < 4 * N_NODES) ((int*)g_deg)[i] = 1;   // self-loop
}

__global__ void k_count(const int* __restrict__ c0, const int* __restrict__ c1,
                        const int* __restrict__ c2, const int* __restrict__ c3) {
    int set = blockIdx.y;
    const int* col = set == 0 ? c0 : set == 1 ? c1 : set == 2 ? c2 : c3;
    int i = blockIdx.x * blockDim.x + threadIdx.x;
    if (i < NE) atomicAdd(&g_deg[set][__ldg(col + i)], 1);
}

__global__ void k_dis() {
    int i = blockIdx.x * blockDim.x + threadIdx.x;
    if (i < 4 * N_NODES)
        ((float*)g_dis)[i] = rsqrtf((float)((const int*)g_deg)[i]);
}

// agg[v][s*256+c] = x[v][c] / deg[s][v]   (self-loop term; overwrites old data)
__global__ void k_init_agg(const float* __restrict__ x) {
    int t = blockIdx.x * blockDim.x + threadIdx.x;
    if (t >= N_NODES * 64) return;
    int v = t >> 6, c4 = t & 63;
    float4 xv = __ldg((const float4*)x + (size_t)v * 64 + c4);
    float4* dst = (float4*)(g_agg + (size_t)v * K4) + c4;
#pragma unroll
    for (int s = 0; s < 4; s++) {
        float inv = 1.0f / (float)g_deg[s][v];
        float4 o = make_float4(xv.x * inv, xv.y * inv, xv.z * inv, xv.w * inv);
        dst[s * 64] = o;
    }
}

// one warp per edge: gather x[row]*norm, red-add into agg[col] (set's 256-slice)
__global__ __launch_bounds__(256)
void k_scatter(const int* __restrict__ e0, const int* __restrict__ e1,
               const int* __restrict__ e2, const int* __restrict__ e3,
               const float* __restrict__ x) {
    int set = blockIdx.y;
    const int* e = set == 0 ? e0 : set == 1 ? e1 : set == 2 ? e2 : e3;
    int w = (blockIdx.x * blockDim.x + threadIdx.x) >> 5;
    int lane = threadIdx.x & 31;
    if (w >= NE) return;
    int row = __ldg(e + w);        // source
    int col = __ldg(e + NE + w);   // target
    float norm = g_dis[set][row] * g_dis[set][col];
    const float4* xr = (const float4*)(x + (size_t)row * C);
    float* dst = g_agg + (size_t)col * K4 + set * C;
#pragma unroll
    for (int i = 0; i < 2; i++) {
        int c4 = lane + i * 32;
        float4 v = __ldg(xr + c4);
        v.x *= norm; v.y *= norm; v.z *= norm; v.w *= norm;
        red_add_v4(dst + c4 * 4, v);
    }
}

// Wcat[(s*256+k)*256+j] = W_s[k][j] * p_{s+2}[j];  bias[j] = sum_s b_s[j]*p_{s+2}[j]
__global__ void k_prep(const float* __restrict__ W1, const float* __restrict__ W2,
                       const float* __restrict__ W3, const float* __restrict__ W4,
                       const float* __restrict__ b1, const float* __restrict__ b2,
                       const float* __restrict__ b3, const float* __restrict__ b4,
                       const float* __restrict__ p2, const float* __restrict__ p3,
                       const float* __restrict__ p4, const float* __restrict__ p5) {
    int t = blockIdx.x * blockDim.x + threadIdx.x;
    if (t >= K4 * C) return;
    int j = t & 255;
    int sk = t >> 8;
    int s = sk >> 8, k = sk & 255;
    const float* W = s == 0 ? W1 : s == 1 ? W2 : s == 2 ? W3 : W4;
    const float* p = s == 0 ? p2 : s == 1 ? p3 : s == 2 ? p4 : p5;
    g_Wcat[t] = __ldg(W + k * C + j) * __ldg(p + j);
    if (t < C)
        g_bias[t] = __ldg(b1 + t) * __ldg(p2 + t) + __ldg(b2 + t) * __ldg(p3 + t)
                  + __ldg(b3 + t) * __ldg(p4 + t) + __ldg(b4 + t) * __ldg(p5 + t);
}

// out[N,256] = agg[N,1024] @ Wcat[1024,256] + x0c*p0 + x1c*p1 + bias
#define BM 128
#define BN 128
#define BK 8
#define TM 8
#define TN 8

__global__ __launch_bounds__(256)
void k_gemm(const float* __restrict__ x,
            const float* __restrict__ t0, const float* __restrict__ t1,
            const float* __restrict__ p0, const float* __restrict__ p1,
            float* __restrict__ out) {
    __shared__ float As[BK][BM];
    __shared__ float Bs[BK][BN];
    int bm = blockIdx.x;     // 782
    int bn = blockIdx.y;     // 2
    int tid = threadIdx.x;

    const float* A = g_agg + (size_t)bm * BM * K4;
    const float* B = g_Wcat + bn * BN;

    float acc[TM][TN];
#pragma unroll
    for (int i = 0; i < TM; i++)
#pragma unroll
        for (int j = 0; j < TN; j++) acc[i][j] = 0.0f;

    int arow = tid >> 1, ak = (tid & 1) * 4;
    int brow = tid >> 5, bcol = (tid & 31) * 4;
    int tx = tid & 15, ty = tid >> 4;

    for (int k0 = 0; k0 < K4; k0 += BK) {
        float4 av = *(const float4*)(A + (size_t)arow * K4 + k0 + ak);
        As[ak + 0][arow] = av.x; As[ak + 1][arow] = av.y;
        As[ak + 2][arow] = av.z; As[ak + 3][arow] = av.w;
        float4 bv = *(const float4*)(B + (size_t)(k0 + brow) * C + bcol);
        *(float4*)(&Bs[brow][bcol]) = bv;
        __syncthreads();
#pragma unroll
        for (int kk = 0; kk < BK; kk++) {
            float ar[TM], br[TN];
#pragma unroll
            for (int i = 0; i < TM; i++) ar[i] = As[kk][ty * TM + i];
#pragma unroll
            for (int j = 0; j < TN; j++) br[j] = Bs[kk][tx * TN + j];
#pragma unroll
            for (int i = 0; i < TM; i++)
#pragma unroll
                for (int j = 0; j < TN; j++)
                    acc[i][j] += ar[i] * br[j];
        }
        __syncthreads();
    }

    int col0 = bn * BN + tx * TN;
    float pb[TN], p0v[TN], p1v[TN];
#pragma unroll
    for (int j = 0; j < TN; j++) {
        pb[j] = g_bias[col0 + j];
        p0v[j] = __ldg(p0 + col0 + j);
        p1v[j] = __ldg(p1 + col0 + j);
    }
#pragma unroll
    for (int i = 0; i < TM; i++) {
        int v = bm * BM + ty * TM + i;
        if (v < N_NODES) {
            float xv0 = __ldg(x + (size_t)v * C);
            float a0 = __ldg(t0 + v) * xv0;
            float a1 = __ldg(t1 + v) * xv0;
            float* o = out + (size_t)v * C + col0;
#pragma unroll
            for (int j = 0; j < TN; j++)
                o[j] = acc[i][j] + a0 * p0v[j] + a1 * p1v[j] + pb[j];
        }
    }
}

// ---------------- launch ----------------------------------------------------
extern "C" void kernel_launch(void* const* d_in, const int* in_sizes, int n_in,
                              void* d_out, int out_size) {
    const float* x   = (const float*)d_in[0];
    const int*   e00 = (const int*)d_in[1];
    const int*   e01 = (const int*)d_in[2];
    const int*   e10 = (const int*)d_in[3];
    const int*   e11 = (const int*)d_in[4];
    const float* t0  = (const float*)d_in[5];
    const float* t1  = (const float*)d_in[6];
    const float* W1  = (const float*)d_in[7];
    const float* b1  = (const float*)d_in[8];
    const float* W2  = (const float*)d_in[9];
    const float* b2  = (const float*)d_in[10];
    const float* W3  = (const float*)d_in[11];
    const float* b3  = (const float*)d_in[12];
    const float* W4  = (const float*)d_in[13];
    const float* b4  = (const float*)d_in[14];
    const float* p0  = (const float*)d_in[15];
    const float* p1  = (const float*)d_in[16];
    const float* p2  = (const float*)d_in[17];
    const float* p3  = (const float*)d_in[18];
    const float* p4  = (const float*)d_in[19];
    const float* p5  = (const float*)d_in[20];
    float* out = (float*)d_out;

    k_init_deg<<<(4 * N_NODES + 255) / 256, 256>>>();
    k_count<<<dim3((NE + 255) / 256, 4), 256>>>(e00 + NE, e01 + NE, e10 + NE, e11 + NE);
    k_dis<<<(4 * N_NODES + 255) / 256, 256>>>();
    k_init_agg<<<(N_NODES * 64 + 255) / 256, 256>>>(x);
    k_scatter<<<dim3((NE * 32 + 255) / 256, 4), 256>>>(e00, e01, e10, e11, x);
    k_prep<<<(K4 * C + 255) / 256, 256>>>(W1, W2, W3, W4, b1, b2, b3, b4, p2, p3, p4, p5);
    k_gemm<<<dim3(NPAD / BM, C / BN), 256>>>(x, t0, t1, p0, p1, out);
}

// round 12
// speedup vs baseline: 1.4286x; 1.4286x over previous
#include <cuda_runtime.h>

#define N_NODES 100000
#define NPAD    100096          // 782 * 128
#define NE      500000
#define C       256
#define K4      1024

// ---------------- scratch (device globals) ----------------------------------
__device__ __align__(16) float g_hcat[(size_t)NPAD * K4];  // [NPAD,1024] transformed feats
__device__ int   g_deg[4][N_NODES];
__device__ float g_dis[4][N_NODES];
__device__ __align__(16) float g_Wcat[C * K4];             // [256 (k), 1024 (n)]
__device__ __align__(16) float g_bias[C];

// ---------------- helpers ----------------------------------------------------
__device__ __forceinline__ void red_add_v4(float* a, float4 v) {
    asm volatile("red.global.add.v4.f32 [%0], {%1,%2,%3,%4};"
                 :: "l"(a), "f"(v.x), "f"(v.y), "f"(v.z), "f"(v.w) : "memory");
}
__device__ __forceinline__ void red_add_v2(float* a, float x, float y) {
    asm volatile("red.global.add.v2.f32 [%0], {%1,%2};"
                 :: "l"(a), "f"(x), "f"(y) : "memory");
}
__device__ __forceinline__ float tf32r(float f) {
    unsigned u; asm("cvt.rna.tf32.f32 %0, %1;" : "=r"(u) : "f"(f));
    return __uint_as_float(u);
}

// ---------------- small kernels ----------------------------------------------
__global__ void k_init_deg() {
    int i = blockIdx.x * blockDim.x + threadIdx.x;
    if (i < 4 * N_NODES) ((int*)g_deg)[i] = 1;
}

__global__ void k_count(const int* __restrict__ c0, const int* __restrict__ c1,
                        const int* __restrict__ c2, const int* __restrict__ c3) {
    int set = blockIdx.y;
    const int* col = set == 0 ? c0 : set == 1 ? c1 : set == 2 ? c2 : c3;
    int i = blockIdx.x * blockDim.x + threadIdx.x;
    if (i < NE) atomicAdd(&g_deg[set][__ldg(col + i)], 1);
}

__global__ void k_dis() {
    int i = blockIdx.x * blockDim.x + threadIdx.x;
    if (i < 4 * N_NODES)
        ((float*)g_dis)[i] = rsqrtf((float)((const int*)g_deg)[i]);
}

// Wcat[k][s*256+j] = W_s[k][j] * p_{s+2}[j];  bias[j] = sum_s b_s[j]*p_{s+2}[j]
__global__ void k_prep(const float* __restrict__ W1, const float* __restrict__ W2,
                       const float* __restrict__ W3, const float* __restrict__ W4,
                       const float* __restrict__ b1, const float* __restrict__ b2,
                       const float* __restrict__ b3, const float* __restrict__ b4,
                       const float* __restrict__ p2, const float* __restrict__ p3,
                       const float* __restrict__ p4, const float* __restrict__ p5) {
    int t = blockIdx.x * blockDim.x + threadIdx.x;
    if (t >= C * K4) return;
    int k = t >> 10, n = t & 1023, s = n >> 8, j = n & 255;
    const float* W = s == 0 ? W1 : s == 1 ? W2 : s == 2 ? W3 : W4;
    const float* p = s == 0 ? p2 : s == 1 ? p3 : s == 2 ? p4 : p5;
    g_Wcat[t] = __ldg(W + k * C + j) * __ldg(p + j);
    if (t < C)
        g_bias[t] = __ldg(b1 + t) * __ldg(p2 + t) + __ldg(b2 + t) * __ldg(p3 + t)
                  + __ldg(b3 + t) * __ldg(p4 + t) + __ldg(b4 + t) * __ldg(p5 + t);
}

// out[v][j] = bias[j] + t0[v]*x[v,0]*p0[j] + t1[v]*x[v,0]*p1[j]
__global__ void k_init_out(const float* __restrict__ x,
                           const float* __restrict__ t0, const float* __restrict__ t1,
                           const float* __restrict__ p0, const float* __restrict__ p1,
                           float* __restrict__ out) {
    int t = blockIdx.x * blockDim.x + threadIdx.x;
    if (t >= N_NODES * 64) return;
    int v = t >> 6, q = t & 63;
    float xv = __ldg(x + (size_t)v * C);
    float a0 = __ldg(t0 + v) * xv;
    float a1 = __ldg(t1 + v) * xv;
    float4 bb = __ldg((const float4*)g_bias + q);
    float4 P0 = __ldg((const float4*)p0 + q);
    float4 P1 = __ldg((const float4*)p1 + q);
    float4 o;
    o.x = bb.x + a0 * P0.x + a1 * P1.x;
    o.y = bb.y + a0 * P0.y + a1 * P1.y;
    o.z = bb.z + a0 * P0.z + a1 * P1.z;
    o.w = bb.w + a0 * P0.w + a1 * P1.w;
    ((float4*)out)[(size_t)v * 64 + q] = o;
}

// ---------------- tf32 tensor-core GEMM: hcat = x @ Wcat --------------------
// M=100096, K=256, N=1024. Block tile 128x128, BK=16, 8 warps (2M x 4N),
// warp tile 64x32 via m16n8k8 tf32 mma. Epilogue writes hcat and red-adds
// the self-loop term hcat[v]/deg_s[v] into out.
#define MMA8(d, a, b)                                                          \
    asm volatile("mma.sync.aligned.m16n8k8.row.col.f32.tf32.tf32.f32 "         \
                 "{%0,%1,%2,%3},{%4,%5,%6,%7},{%8,%9},{%0,%1,%2,%3};"          \
                 : "+f"(d[0]), "+f"(d[1]), "+f"(d[2]), "+f"(d[3])              \
                 : "r"(a[0]), "r"(a[1]), "r"(a[2]), "r"(a[3]),                 \
                   "r"(b[0]), "r"(b[1]))

__global__ __launch_bounds__(256, 1)
void k_gemm(const float* __restrict__ x, float* __restrict__ out) {
    __shared__ float As[128][20];   // [m][k], pad 20 -> conflict-free frag loads
    __shared__ float Bs[16][136];   // [k][n], pad 136 -> conflict-free
    int bm = blockIdx.x, bn = blockIdx.y;
    int tid = threadIdx.x, lane = tid & 31, warp = tid >> 5;
    int wm = warp & 1, wn = warp >> 1;
    int s = bn >> 1;                 // edge-set this 128-col slab belongs to

    // A gmem load: each thread stages TWO float4s: rows arow and arow+64
    // (128 rows x 16 k = 512 float4s, 256 threads -> 2 each)
    int arow = tid >> 2, aq = (tid & 3) * 4;
    int grow0 = bm * 128 + arow;
    int grow1 = grow0 + 64;
    bool av0 = grow0 < N_NODES, av1 = grow1 < N_NODES;
    const float* ap0 = x + (size_t)grow0 * C + aq;
    const float* ap1 = x + (size_t)grow1 * C + aq;

    // B gmem load: two float4 per thread: (k=tid>>5, q=tid&31) and (k+8, q)
    int bk = tid >> 5, bq = tid & 31;
    const float* bp = g_Wcat + (size_t)bn * 128 + bq * 4;

    float4 aR0 = av0 ? __ldg((const float4*)ap0) : make_float4(0, 0, 0, 0);
    float4 aR1 = av1 ? __ldg((const float4*)ap1) : make_float4(0, 0, 0, 0);
    float4 bR0 = __ldg((const float4*)(bp + (size_t)bk * K4));
    float4 bR1 = __ldg((const float4*)(bp + (size_t)(bk + 8) * K4));

    float acc[4][4][4];
#pragma unroll
    for (int i = 0; i < 4; i++)
#pragma unroll
        for (int j = 0; j < 4; j++)
#pragma unroll
            for (int r = 0; r < 4; r++) acc[i][j][r] = 0.0f;

    for (int k0 = 0; k0 < 256; k0 += 16) {
        As[arow][aq + 0] = tf32r(aR0.x);
        As[arow][aq + 1] = tf32r(aR0.y);
        As[arow][aq + 2] = tf32r(aR0.z);
        As[arow][aq + 3] = tf32r(aR0.w);
        As[arow + 64][aq + 0] = tf32r(aR1.x);
        As[arow + 64][aq + 1] = tf32r(aR1.y);
        As[arow + 64][aq + 2] = tf32r(aR1.z);
        As[arow + 64][aq + 3] = tf32r(aR1.w);
        float* b0 = &Bs[bk][bq * 4];
        b0[0] = tf32r(bR0.x); b0[1] = tf32r(bR0.y);
        b0[2] = tf32r(bR0.z); b0[3] = tf32r(bR0.w);
        float* b1 = &Bs[bk + 8][bq * 4];
        b1[0] = tf32r(bR1.x); b1[1] = tf32r(bR1.y);
        b1[2] = tf32r(bR1.z); b1[3] = tf32r(bR1.w);
        __syncthreads();

        if (k0 + 16 < 256) {
            aR0 = av0 ? __ldg((const float4*)(ap0 + k0 + 16)) : make_float4(0, 0, 0, 0);
            aR1 = av1 ? __ldg((const float4*)(ap1 + k0 + 16)) : make_float4(0, 0, 0, 0);
            bR0 = __ldg((const float4*)(bp + (size_t)(k0 + 16 + bk) * K4));
            bR1 = __ldg((const float4*)(bp + (size_t)(k0 + 24 + bk) * K4));
        }

#pragma unroll
        for (int kk = 0; kk < 2; kk++) {
            int ka = kk * 8 + (lane & 3);
            unsigned a[4][4], b[4][2];
#pragma unroll
            for (int mi = 0; mi < 4; mi++) {
                int r = wm * 64 + mi * 16 + (lane >> 2);
                a[mi][0] = __float_as_uint(As[r][ka]);
                a[mi][1] = __float_as_uint(As[r + 8][ka]);
                a[mi][2] = __float_as_uint(As[r][ka + 4]);
                a[mi][3] = __float_as_uint(As[r + 8][ka + 4]);
            }
#pragma unroll
            for (int ni = 0; ni < 4; ni++) {
                int n = wn * 32 + ni * 8 + (lane >> 2);
                b[ni][0] = __float_as_uint(Bs[ka][n]);
                b[ni][1] = __float_as_uint(Bs[ka + 4][n]);
            }
#pragma unroll
            for (int mi = 0; mi < 4; mi++)
#pragma unroll
                for (int ni = 0; ni < 4; ni++) MMA8(acc[mi][ni], a[mi], b[ni]);
        }
        __syncthreads();
    }

    // epilogue: write hcat + red-add self-loop term into out
    int cbase = bn * 128 + wn * 32 + 2 * (lane & 3);
#pragma unroll
    for (int mi = 0; mi < 4; mi++) {
        int r0 = bm * 128 + wm * 64 + mi * 16 + (lane >> 2);
#pragma unroll
        for (int h = 0; h < 2; h++) {
            int r = r0 + h * 8;
            if (r < N_NODES) {
                float inv = 1.0f / (float)g_deg[s][r];
                float* hrow = g_hcat + (size_t)r * K4;
                float* orow = out + (size_t)r * C;
#pragma unroll
                for (int ni = 0; ni < 4; ni++) {
                    int c = cbase + ni * 8;
                    float v0 = acc[mi][ni][h * 2 + 0];
                    float v1 = acc[mi][ni][h * 2 + 1];
                    *(float2*)(hrow + c) = make_float2(v0, v1);
                    red_add_v2(orow + (c & 255), v0 * inv, v1 * inv);
                }
            }
        }
    }
}

// ---------------- edge scatter: out[col] += hcat_s[row] * norm ---------------
__global__ __launch_bounds__(256)
void k_scatter(const int* __restrict__ e0, const int* __restrict__ e1,
               const int* __restrict__ e2, const int* __restrict__ e3,
               float* __restrict__ out) {
    int set = blockIdx.y;
    const int* e = set == 0 ? e0 : set == 1 ? e1 : set == 2 ? e2 : e3;
    int w = (blockIdx.x * blockDim.x + threadIdx.x) >> 5;
    int lane = threadIdx.x & 31;
    if (w >= NE) return;
    int row = __ldg(e + w);
    int col = __ldg(e + NE + w);
    float norm = g_dis[set][row] * g_dis[set][col];
    const float4* hr = (const float4*)(g_hcat + (size_t)row * K4 + set * C);
    float* dst = out + (size_t)col * C;
#pragma unroll
    for (int i = 0; i < 2; i++) {
        int c4 = lane + i * 32;
        float4 v = __ldg(hr + c4);
        v.x *= norm; v.y *= norm; v.z *= norm; v.w *= norm;
        red_add_v4(dst + c4 * 4, v);
    }
}

// ---------------- launch ------------------------------------------------------
extern "C" void kernel_launch(void* const* d_in, const int* in_sizes, int n_in,
                              void* d_out, int out_size) {
    const float* x   = (const float*)d_in[0];
    const int*   e00 = (const int*)d_in[1];
    const int*   e01 = (const int*)d_in[2];
    const int*   e10 = (const int*)d_in[3];
    const int*   e11 = (const int*)d_in[4];
    const float* t0  = (const float*)d_in[5];
    const float* t1  = (const float*)d_in[6];
    const float* W1  = (const float*)d_in[7];
    const float* b1  = (const float*)d_in[8];
    const float* W2  = (const float*)d_in[9];
    const float* b2  = (const float*)d_in[10];
    const float* W3  = (const float*)d_in[11];
    const float* b3  = (const float*)d_in[12];
    const float* W4  = (const float*)d_in[13];
    const float* b4  = (const float*)d_in[14];
    const float* p0  = (const float*)d_in[15];
    const float* p1  = (const float*)d_in[16];
    const float* p2  = (const float*)d_in[17];
    const float* p3  = (const float*)d_in[18];
    const float* p4  = (const float*)d_in[19];
    const float* p5  = (const float*)d_in[20];
    float* out = (float*)d_out;

    k_init_deg<<<(4 * N_NODES + 255) / 256, 256>>>();
    k_count<<<dim3((NE + 255) / 256, 4), 256>>>(e00 + NE, e01 + NE, e10 + NE, e11 + NE);
    k_dis<<<(4 * N_NODES + 255) / 256, 256>>>();
    k_prep<<<(C * K4 + 255) / 256, 256>>>(W1, W2, W3, W4, b1, b2, b3, b4, p2, p3, p4, p5);
    k_init_out<<<(N_NODES * 64 + 255) / 256, 256>>>(x, t0, t1, p0, p1, out);
    k_gemm<<<dim3(NPAD / 128, 8), 256>>>(x, out);
    k_scatter<<<dim3((NE + 7) / 8, 4), 256>>>(e00, e01, e10, e11, out);
}

// round 14
// speedup vs baseline: 2.1721x; 1.5204x over previous
#include <cuda_runtime.h>

#define N_NODES 100000
#define NPAD    100096          // 782 * 128
#define NE      500000
#define C       256
#define K4      1024
#define M4      (4 * N_NODES)   // 400000 (set,node) pairs
#define NBLK    ((M4 + 511) / 512)   // 782 scan blocks

// ---------------- scratch (device globals) ----------------------------------
__device__ __align__(16) float g_agg[(size_t)NPAD * K4];   // [NPAD,1024] aggregated x
__device__ int   g_ecnt[M4];         // edge count per (set,node)  (zeroed each run)
__device__ float g_dis[M4];          // rsqrt(deg) per (set,node)
__device__ int   g_off[M4];          // CSR start offsets (global over 4*NE)
__device__ int   g_cur[M4];          // fill cursor; after fill == end offset
__device__ int   g_bsum[NBLK];
__device__ int   g_bbase[NBLK];
__device__ int   g_csr[4 * NE];      // source row per CSR slot
__device__ __align__(16) float g_Wcat[K4 * C];   // [K=1024][N=256]
__device__ __align__(16) float g_bias[C];

// ---------------- helpers ----------------------------------------------------
__device__ __forceinline__ float tf32r(float f) {
    unsigned u; asm("cvt.rna.tf32.f32 %0, %1;" : "=r"(u) : "f"(f));
    return __uint_as_float(u);
}

// ---------------- CSR build --------------------------------------------------
__global__ void k_zero() {
    int i = blockIdx.x * blockDim.x + threadIdx.x;
    if (i < M4) g_ecnt[i] = 0;
}

__global__ void k_count(const int* __restrict__ c0, const int* __restrict__ c1,
                        const int* __restrict__ c2, const int* __restrict__ c3) {
    int set = blockIdx.y;
    const int* col = set == 0 ? c0 : set == 1 ? c1 : set == 2 ? c2 : c3;
    int i = blockIdx.x * blockDim.x + threadIdx.x;
    if (i < NE) atomicAdd(&g_ecnt[set * N_NODES + __ldg(col + i)], 1);
}

__global__ void k_dis() {
    int i = blockIdx.x * blockDim.x + threadIdx.x;
    if (i < M4) g_dis[i] = rsqrtf((float)(g_ecnt[i] + 1));   // +1 self-loop
}

__global__ void k_scan1() {
    __shared__ int sm[512];
    int t = threadIdx.x, i = blockIdx.x * 512 + t;
    sm[t] = (i < M4) ? g_ecnt[i] : 0;
    __syncthreads();
    for (int d = 256; d > 0; d >>= 1) {
        if (t < d) sm[t] += sm[t + d];
        __syncthreads();
    }
    if (t == 0) g_bsum[blockIdx.x] = sm[0];
}

__global__ void k_scan2() {
    __shared__ int sm[1024];
    int t = threadIdx.x;
    int v = (t < NBLK) ? g_bsum[t] : 0;
    sm[t] = v;
    __syncthreads();
    for (int d = 1; d < 1024; d <<= 1) {
        int a = (t >= d) ? sm[t - d] : 0;
        __syncthreads();
        sm[t] += a;
        __syncthreads();
    }
    if (t < NBLK) g_bbase[t] = sm[t] - v;   // exclusive
}

__global__ void k_scan3() {
    __shared__ int sm[512];
    int t = threadIdx.x, i = blockIdx.x * 512 + t;
    int v = (i < M4) ? g_ecnt[i] : 0;
    sm[t] = v;
    __syncthreads();
    for (int d = 1; d < 512; d <<= 1) {
        int a = (t >= d) ? sm[t - d] : 0;
        __syncthreads();
        sm[t] += a;
        __syncthreads();
    }
    if (i < M4) {
        int excl = sm[t] - v + g_bbase[blockIdx.x];
        g_off[i] = excl;
        g_cur[i] = excl;
    }
}

__global__ void k_fill(const int* __restrict__ e0, const int* __restrict__ e1,
                       const int* __restrict__ e2, const int* __restrict__ e3) {
    int set = blockIdx.y;
    const int* e = set == 0 ? e0 : set == 1 ? e1 : set == 2 ? e2 : e3;
    int i = blockIdx.x * blockDim.x + threadIdx.x;
    if (i >= NE) return;
    int row = __ldg(e + i);
    int col = __ldg(e + NE + i);
    int pos = atomicAdd(&g_cur[set * N_NODES + col], 1);
    g_csr[pos] = row;
}

// Wcat[(s*256+k)*256+j] = W_s[k][j] * p_{s+2}[j];  bias[j] = sum_s b_s[j]*p_{s+2}[j]
__global__ void k_prep(const float* __restrict__ W1, const float* __restrict__ W2,
                       const float* __restrict__ W3, const float* __restrict__ W4,
                       const float* __restrict__ b1, const float* __restrict__ b2,
                       const float* __restrict__ b3, const float* __restrict__ b4,
                       const float* __restrict__ p2, const float* __restrict__ p3,
                       const float* __restrict__ p4, const float* __restrict__ p5) {
    int t = blockIdx.x * blockDim.x + threadIdx.x;
    if (t >= K4 * C) return;
    int j = t & 255;
    int sk = t >> 8;
    int s = sk >> 8, k = sk & 255;
    const float* W = s == 0 ? W1 : s == 1 ? W2 : s == 2 ? W3 : W4;
    const float* p = s == 0 ? p2 : s == 1 ? p3 : s == 2 ? p4 : p5;
    g_Wcat[t] = __ldg(W + k * C + j) * __ldg(p + j);
    if (t < C)
        g_bias[t] = __ldg(b1 + t) * __ldg(p2 + t) + __ldg(b2 + t) * __ldg(p3 + t)
                  + __ldg(b3 + t) * __ldg(p4 + t) + __ldg(b4 + t) * __ldg(p5 + t);
}

// ---------------- gather: agg[v][s*256+:] = x[v]/deg + sum_e x[src]*norm ----
__global__ __launch_bounds__(256)
void k_gather(const float* __restrict__ x) {
    int w = (blockIdx.x * blockDim.x + threadIdx.x) >> 5;
    int lane = threadIdx.x & 31;
    if (w >= M4) return;
    int v = w >> 2, s = w & 3;           // 4 consecutive warps = one node's 4 slices
    int idx = s * N_NODES + v;
    int p = g_off[idx];
    int end = g_cur[idx];                // cursor after fill == end
    float dv = g_dis[idx];
    const float* dis_s = g_dis + s * N_NODES;

    const float4* xv = (const float4*)(x + (size_t)v * C);
    float inv = dv * dv;                 // 1/deg (self-loop norm)
    float4 a0 = __ldg(xv + lane);
    float4 a1 = __ldg(xv + lane + 32);
    a0.x *= inv; a0.y *= inv; a0.z *= inv; a0.w *= inv;
    a1.x *= inv; a1.y *= inv; a1.z *= inv; a1.w *= inv;

    int row = (p < end) ? __ldg(g_csr + p) : 0;
    while (p < end) {
        int nrow = (p + 1 < end) ? __ldg(g_csr + p + 1) : 0;
        float norm = dv * __ldg(dis_s + row);
        const float4* xr = (const float4*)(x + (size_t)row * C);
        float4 b0 = __ldg(xr + lane);
        float4 b1 = __ldg(xr + lane + 32);
        a0.x += b0.x * norm; a0.y += b0.y * norm;
        a0.z += b0.z * norm; a0.w += b0.w * norm;
        a1.x += b1.x * norm; a1.y += b1.y * norm;
        a1.z += b1.z * norm; a1.w += b1.w * norm;
        row = nrow;
        ++p;
    }
    float4* dst = (float4*)(g_agg + (size_t)v * K4 + s * C);
    dst[lane] = a0;
    dst[lane + 32] = a1;
}

// ---------------- tf32 GEMM: out = agg[N,1024] @ Wcat[1024,256] + epilogue --
#define MMA8(d, a, b)                                                          \
    asm volatile("mma.sync.aligned.m16n8k8.row.col.f32.tf32.tf32.f32 "         \
                 "{%0,%1,%2,%3},{%4,%5,%6,%7},{%8,%9},{%0,%1,%2,%3};"          \
                 : "+f"(d[0]), "+f"(d[1]), "+f"(d[2]), "+f"(d[3])              \
                 : "r"(a[0]), "r"(a[1]), "r"(a[2]), "r"(a[3]),                 \
                   "r"(b[0]), "r"(b[1]))

__global__ __launch_bounds__(256, 1)
void k_gemm(const float* __restrict__ x,
            const float* __restrict__ t0, const float* __restrict__ t1,
            const float* __restrict__ p0, const float* __restrict__ p1,
            float* __restrict__ out) {
    __shared__ float As[128][20];
    __shared__ float Bs[16][136];
    int bn = blockIdx.x, bm = blockIdx.y;   // bn fastest -> A slab L2 reuse
    int tid = threadIdx.x, lane = tid & 31, warp = tid >> 5;
    int wm = warp & 1, wn = warp >> 1;

    // A staging: two float4 per thread, rows arow and arow+64, 16 k-cols
    int arow = tid >> 2, aq = (tid & 3) * 4;
    const float* ap0 = g_agg + (size_t)(bm * 128 + arow) * K4 + aq;
    const float* ap1 = ap0 + (size_t)64 * K4;
    // B staging: rows bk and bk+8 of the 16-row B tile, 128-col slab
    int bk = tid >> 5, bq = tid & 31;
    const float* bp = g_Wcat + bn * 128 + bq * 4;

    float4 aR0 = __ldg((const float4*)ap0);
    float4 aR1 = __ldg((const float4*)ap1);
    float4 bR0 = __ldg((const float4*)(bp + (size_t)bk * C));
    float4 bR1 = __ldg((const float4*)(bp + (size_t)(bk + 8) * C));

    float acc[4][4][4];
#pragma unroll
    for (int i = 0; i < 4; i++)
#pragma unroll
        for (int j = 0; j < 4; j++)
#pragma unroll
            for (int r = 0; r < 4; r++) acc[i][j][r] = 0.0f;

    for (int k0 = 0; k0 < K4; k0 += 16) {
        As[arow][aq + 0] = tf32r(aR0.x);
        As[arow][aq + 1] = tf32r(aR0.y);
        As[arow][aq + 2] = tf32r(aR0.z);
        As[arow][aq + 3] = tf32r(aR0.w);
        As[arow + 64][aq + 0] = tf32r(aR1.x);
        As[arow + 64][aq + 1] = tf32r(aR1.y);
        As[arow + 64][aq + 2] = tf32r(aR1.z);
        As[arow + 64][aq + 3] = tf32r(aR1.w);
        float* b0 = &Bs[bk][bq * 4];
        b0[0] = tf32r(bR0.x); b0[1] = tf32r(bR0.y);
        b0[2] = tf32r(bR0.z); b0[3] = tf32r(bR0.w);
        float* b1 = &Bs[bk + 8][bq * 4];
        b1[0] = tf32r(bR1.x); b1[1] = tf32r(bR1.y);
        b1[2] = tf32r(bR1.z); b1[3] = tf32r(bR1.w);
        __syncthreads();

        if (k0 + 16 < K4) {
            aR0 = __ldg((const float4*)(ap0 + k0 + 16));
            aR1 = __ldg((const float4*)(ap1 + k0 + 16));
            bR0 = __ldg((const float4*)(bp + (size_t)(k0 + 16 + bk) * C));
            bR1 = __ldg((const float4*)(bp + (size_t)(k0 + 24 + bk) * C));
        }

#pragma unroll
        for (int kk = 0; kk < 2; kk++) {
            int ka = kk * 8 + (lane & 3);
            unsigned a[4][4], b[4][2];
#pragma unroll
            for (int mi = 0; mi < 4; mi++) {
                int r = wm * 64 + mi * 16 + (lane >> 2);
                a[mi][0] = __float_as_uint(As[r][ka]);
                a[mi][1] = __float_as_uint(As[r + 8][ka]);
                a[mi][2] = __float_as_uint(As[r][ka + 4]);
                a[mi][3] = __float_as_uint(As[r + 8][ka + 4]);
            }
#pragma unroll
            for (int ni = 0; ni < 4; ni++) {
                int n = wn * 32 + ni * 8 + (lane >> 2);
                b[ni][0] = __float_as_uint(Bs[ka][n]);
                b[ni][1] = __float_as_uint(Bs[ka + 4][n]);
            }
#pragma unroll
            for (int mi = 0; mi < 4; mi++)
#pragma unroll
                for (int ni = 0; ni < 4; ni++) MMA8(acc[mi][ni], a[mi], b[ni]);
        }
        __syncthreads();
    }

    // epilogue: out = acc + bias + t0*x0*p0 + t1*x0*p1  (plain stores)
    int cbase = bn * 128 + wn * 32 + 2 * (lane & 3);
    float2 pb[4], P0[4], P1[4];
#pragma unroll
    for (int ni = 0; ni < 4; ni++) {
        int c = cbase + ni * 8;
        pb[ni] = *(const float2*)(g_bias + c);
        P0[ni] = *(const float2*)(p0 + c);
        P1[ni] = *(const float2*)(p1 + c);
    }
#pragma unroll
    for (int mi = 0; mi < 4; mi++) {
#pragma unroll
        for (int h = 0; h < 2; h++) {
            int r = bm * 128 + wm * 64 + mi * 16 + h * 8 + (lane >> 2);
            if (r < N_NODES) {
                float xv0 = __ldg(x + (size_t)r * C);
                float a0 = __ldg(t0 + r) * xv0;
                float a1 = __ldg(t1 + r) * xv0;
                float* orow = out + (size_t)r * C;
#pragma unroll
                for (int ni = 0; ni < 4; ni++) {
                    int c = cbase + ni * 8;
                    float2 o;
                    o.x = acc[mi][ni][h * 2 + 0] + pb[ni].x + a0 * P0[ni].x + a1 * P1[ni].x;
                    o.y = acc[mi][ni][h * 2 + 1] + pb[ni].y + a0 * P0[ni].y + a1 * P1[ni].y;
                    *(float2*)(orow + c) = o;
                }
            }
        }
    }
}

// ---------------- launch ------------------------------------------------------
extern "C" void kernel_launch(void* const* d_in, const int* in_sizes, int n_in,
                              void* d_out, int out_size) {
    const float* x   = (const float*)d_in[0];
    const int*   e00 = (const int*)d_in[1];
    const int*   e01 = (const int*)d_in[2];
    const int*   e10 = (const int*)d_in[3];
    const int*   e11 = (const int*)d_in[4];
    const float* t0  = (const float*)d_in[5];
    const float* t1  = (const float*)d_in[6];
    const float* W1  = (const float*)d_in[7];
    const float* b1  = (const float*)d_in[8];
    const float* W2  = (const float*)d_in[9];
    const float* b2  = (const float*)d_in[10];
    const float* W3  = (const float*)d_in[11];
    const float* b3  = (const float*)d_in[12];
    const float* W4  = (const float*)d_in[13];
    const float* b4  = (const float*)d_in[14];
    const float* p0  = (const float*)d_in[15];
    const float* p1  = (const float*)d_in[16];
    const float* p2  = (const float*)d_in[17];
    const float* p3  = (const float*)d_in[18];
    const float* p4  = (const float*)d_in[19];
    const float* p5  = (const float*)d_in[20];
    float* out = (float*)d_out;

    k_zero<<<(M4 + 255) / 256, 256>>>();
    k_count<<<dim3((NE + 255) / 256, 4), 256>>>(e00 + NE, e01 + NE, e10 + NE, e11 + NE);
    k_dis<<<(M4 + 255) / 256, 256>>>();
    k_scan1<<<NBLK, 512>>>();
    k_scan2<<<1, 1024>>>();
    k_scan3<<<NBLK, 512>>>();
    k_fill<<<dim3((NE + 255) / 256, 4), 256>>>(e00, e01, e10, e11);
    k_prep<<<(K4 * C + 255) / 256, 256>>>(W1, W2, W3, W4, b1, b2, b3, b4, p2, p3, p4, p5);
    k_gather<<<(M4 * 32 + 255) / 256, 256>>>(x);
    k_gemm<<<dim3(2, NPAD / 128), 256>>>(x, t0, t1, p0, p1, out);
}